// round 14
// baseline (speedup 1.0000x reference)
#include <cuda_runtime.h>
#include <cuda_bf16.h>
#include <cuda_fp16.h>
#include <cstdint>

#define NN   512
#define CZc  128
#define RTOT (NN*NN)

// ---------------------------------------------------------------------------
// Scratch planes:
//   g_af/g_bf: fp16 SINGLE-precision channel planes [c][row];
//   per plane c: [i][k] (a), [j][k] (b).
//   g_upd fp32 planes [c][i][j]; g_g fp32 row-major [row][c].
//   g_wh/g_wl: pre-converted weights transposed [n][k] bf16 hi/lo.
//   Weight order: 0=wga 1=wa 2=wgb 3=wb 4=wg 5=wout.
// ---------------------------------------------------------------------------
__device__ __half g_af[(size_t)RTOT * CZc];
__device__ __half g_bf[(size_t)RTOT * CZc];
__device__ float g_g  [(size_t)RTOT * CZc];
__device__ float g_upd[(size_t)RTOT * CZc];
__device__ __nv_bfloat16 g_wh[6 * 128 * 128];
__device__ __nv_bfloat16 g_wl[6 * 128 * 128];

// ---------------------------------------------------------------------------
// Helpers (baseline ISA only)
// ---------------------------------------------------------------------------
__device__ __forceinline__ uint32_t smem_u32(const void* p) {
    uint32_t a;
    asm("{ .reg .u64 t; cvta.to.shared.u64 t, %1; cvt.u32.u64 %0, t; }"
        : "=r"(a) : "l"(p));
    return a;
}
__device__ __forceinline__ float sigmoidf(float x) { return 1.0f / (1.0f + __expf(-x)); }

__device__ __forceinline__ void ldsm4(uint32_t* r, uint32_t addr) {
    asm volatile("ldmatrix.sync.aligned.m8n8.x4.shared.b16 {%0,%1,%2,%3}, [%4];"
                 : "=r"(r[0]), "=r"(r[1]), "=r"(r[2]), "=r"(r[3]) : "r"(addr));
}
__device__ __forceinline__ void mma_bf16(float* c, const uint32_t* a, const uint32_t* b) {
    asm volatile(
        "mma.sync.aligned.m16n8k16.row.col.f32.bf16.bf16.f32 "
        "{%0,%1,%2,%3}, {%4,%5,%6,%7}, {%8,%9}, {%0,%1,%2,%3};"
        : "+f"(c[0]), "+f"(c[1]), "+f"(c[2]), "+f"(c[3])
        : "r"(a[0]), "r"(a[1]), "r"(a[2]), "r"(a[3]), "r"(b[0]), "r"(b[1]));
}
__device__ __forceinline__ void mma_f16(float* c, const uint32_t* a, const uint32_t* b) {
    asm volatile(
        "mma.sync.aligned.m16n8k16.row.col.f32.f16.f16.f32 "
        "{%0,%1,%2,%3}, {%4,%5,%6,%7}, {%8,%9}, {%0,%1,%2,%3};"
        : "+f"(c[0]), "+f"(c[1]), "+f"(c[2]), "+f"(c[3])
        : "r"(a[0]), "r"(a[1]), "r"(a[2]), "r"(a[3]), "r"(b[0]), "r"(b[1]));
}
__device__ __forceinline__ void cp16(uint32_t dst, const void* src) {
    asm volatile("cp.async.cg.shared.global [%0], [%1], 16;"
                 :: "r"(dst), "l"(src) : "memory");
}
#define CP_COMMIT() asm volatile("cp.async.commit_group;" ::: "memory")
#define CP_WAIT0()  asm volatile("cp.async.wait_group 0;"  ::: "memory")

// ---------------------------------------------------------------------------
// (R4) 128x128x128 bf16 hi/lo split mma: A [row][k], B [n][k], both 136-half
// rows (272B stride). 8 warps as 4(m) x 2(n): warp tile 32 x 64. Zeroes acc.
// ---------------------------------------------------------------------------
__device__ __forceinline__ void mma_tile_k128(
    float (*acc)[8][4],
    uint32_t a_h, uint32_t a_l, uint32_t b_h, uint32_t b_l,
    int ib, int jb, int lane)
{
    const int lrow = lane & 15;
    const uint32_t lcolb = (uint32_t)((lane >> 4) & 1) * 16u;

    #pragma unroll
    for (int m = 0; m < 2; ++m)
        #pragma unroll
        for (int q = 0; q < 8; ++q)
            #pragma unroll
            for (int e = 0; e < 4; ++e) acc[m][q][e] = 0.f;

    #pragma unroll
    for (int s = 0; s < 8; ++s) {
        const uint32_t colb = (uint32_t)s * 32u + lcolb;
        uint32_t Bh[4][4], Bl[4][4];
        #pragma unroll
        for (int p = 0; p < 4; ++p) {
            const uint32_t r = (uint32_t)(jb + p*16 + lrow);
            ldsm4(Bh[p], b_h + r*272u + colb);
            ldsm4(Bl[p], b_l + r*272u + colb);
        }
        #pragma unroll
        for (int m = 0; m < 2; ++m) {
            uint32_t Ah[4], Al[4];
            const uint32_t r = (uint32_t)(ib + m*16 + lrow);
            ldsm4(Ah, a_h + r*272u + colb);
            ldsm4(Al, a_l + r*272u + colb);
            #pragma unroll
            for (int q = 0; q < 8; ++q) {
                const int p = q >> 1, o = q & 1;
                uint32_t vh[2] = { Bh[p][o], Bh[p][o + 2] };
                uint32_t vl[2] = { Bl[p][o], Bl[p][o + 2] };
                mma_bf16(acc[m][q], Ah, vh);
                mma_bf16(acc[m][q], Ah, vl);
                mma_bf16(acc[m][q], Al, vh);
            }
        }
    }
}

// (R8) One K-span of 3-product hi/lo MMA for a 32x32 warp tile (k_out).
__device__ __forceinline__ void mma_k(
    float (*acc)[4][4],
    uint32_t aH, uint32_t aL, uint32_t bH, uint32_t bL,
    uint32_t astr, uint32_t bstr, uint32_t acol, int nsteps,
    int ib, int jb, int lane)
{
    const int lr = lane & 15;
    const uint32_t lc = (uint32_t)((lane >> 4) & 1) * 16u;
    for (int s = 0; s < nsteps; ++s) {
        const uint32_t colb = (uint32_t)s * 32u + lc;
        uint32_t Bh[2][4], Bl[2][4];
        #pragma unroll
        for (int p = 0; p < 2; ++p) {
            const uint32_t r = (uint32_t)(jb + p*16 + lr);
            ldsm4(Bh[p], bH + r*bstr + colb);
            ldsm4(Bl[p], bL + r*bstr + colb);
        }
        #pragma unroll
        for (int m = 0; m < 2; ++m) {
            uint32_t Ah[4], Al[4];
            const uint32_t r = (uint32_t)(ib + m*16 + lr);
            ldsm4(Ah, aH + r*astr + acol + colb);
            ldsm4(Al, aL + r*astr + acol + colb);
            #pragma unroll
            for (int q = 0; q < 4; ++q) {
                const int p = q >> 1, o = q & 1;
                uint32_t vh[2] = { Bh[p][o], Bh[p][o + 2] };
                uint32_t vl[2] = { Bl[p][o], Bl[p][o + 2] };
                mma_bf16(acc[m][q], Ah, vh);
                mma_bf16(acc[m][q], Ah, vl);
                mma_bf16(acc[m][q], Al, vh);
            }
        }
    }
}

// ---------------------------------------------------------------------------
// Kernel 0: pre-convert ALL 6 weights to transposed [n][k] bf16 hi/lo.
// ---------------------------------------------------------------------------
__global__ void k_prep(const float* __restrict__ w0, const float* __restrict__ w1,
                       const float* __restrict__ w2, const float* __restrict__ w3,
                       const float* __restrict__ w4, const float* __restrict__ w5)
{
    const float* tbl[6] = { w0, w1, w2, w3, w4, w5 };
    const float* W = tbl[blockIdx.x];
    __nv_bfloat16* oh = g_wh + blockIdx.x * 16384;
    __nv_bfloat16* ol = g_wl + blockIdx.x * 16384;
    for (int idx = threadIdx.x; idx < 16384; idx += 256) {
        const int n = idx >> 7, k = idx & 127;
        const float v = W[k * 128 + n];
        const __nv_bfloat16 h = __float2bfloat16_rn(v);
        oh[idx] = h;
        ol[idx] = __float2bfloat16_rn(v - __bfloat162float(h));
    }
}

// ---------------------------------------------------------------------------
// Kernel 1 (R12 structure): LN1 + 5 projections, cp.async weights.
// ONE change vs R12: a/b epilogue stores SINGLE fp16 planes (g_af/g_bf).
// Dyn smem: region1 = zh/zl (69632 B), region2 = x | (wh/wl) | stage.
// ---------------------------------------------------------------------------
__global__ __launch_bounds__(256, 1) void k_proj(
    const float* __restrict__ x,
    const float* __restrict__ gamma,
    const float* __restrict__ beta)
{
    extern __shared__ char sraw[];
    __nv_bfloat16* zh = (__nv_bfloat16*)sraw;            // [128][136]
    __nv_bfloat16* zl = zh + 128 * 136;
    float*         xs = (float*)(sraw + 69632);          // [128][136]
    __nv_bfloat16* wh = (__nv_bfloat16*)(sraw + 69632);  // [n][136]
    __nv_bfloat16* wl = wh + 128 * 136;
    __half*        stF = (__half*)(sraw + 69632);        // stage [c][136] fp16

    const int tid  = threadIdx.x;
    const int lane = tid & 31, wid = tid >> 5;
    const int r0   = blockIdx.x * 128;

    const uint32_t whb = smem_u32(wh), wlb = smem_u32(wl);

    // load x tile
    #pragma unroll
    for (int e = 0; e < 16; ++e) {
        const int idx = e * 256 + tid;
        const int r = idx >> 5, c4 = (idx & 31) * 4;
        *(float4*)&xs[r * 136 + c4] = *(const float4*)(x + (size_t)(r0 + r) * CZc + c4);
    }
    __syncthreads();

    // LN: warp handles 16 rows; write z as bf16 hi/lo
    {
        const float ga0 = gamma[lane],      ga1 = gamma[lane + 32];
        const float ga2 = gamma[lane + 64], ga3 = gamma[lane + 96];
        const float be0 = beta[lane],       be1 = beta[lane + 32];
        const float be2 = beta[lane + 64],  be3 = beta[lane + 96];
        for (int rr = 0; rr < 16; ++rr) {
            const int r = wid * 16 + rr;
            const float v0 = xs[r*136 + lane];
            const float v1 = xs[r*136 + lane + 32];
            const float v2 = xs[r*136 + lane + 64];
            const float v3 = xs[r*136 + lane + 96];
            float s  = v0 + v1 + v2 + v3;
            float s2 = v0*v0 + v1*v1 + v2*v2 + v3*v3;
            #pragma unroll
            for (int o = 16; o; o >>= 1) {
                s  += __shfl_xor_sync(0xffffffffu, s,  o);
                s2 += __shfl_xor_sync(0xffffffffu, s2, o);
            }
            const float mu   = s * (1.0f / CZc);
            const float var  = s2 * (1.0f / CZc) - mu * mu;
            const float rstd = rsqrtf(var + 1e-5f);
            const float z0 = (v0-mu)*rstd*ga0 + be0;
            const float z1 = (v1-mu)*rstd*ga1 + be1;
            const float z2 = (v2-mu)*rstd*ga2 + be2;
            const float z3 = (v3-mu)*rstd*ga3 + be3;
            #pragma unroll
            for (int j = 0; j < 4; ++j) {
                const float zv = j==0?z0:j==1?z1:j==2?z2:z3;
                const int c = lane + j*32;
                const __nv_bfloat16 h = __float2bfloat16_rn(zv);
                zh[r*136 + c] = h;
                zl[r*136 + c] = __float2bfloat16_rn(zv - __bfloat162float(h));
            }
        }
    }

    const int wi = wid & 3, wj = wid >> 2;
    const int ib = wi * 32, jb = wj * 64;
    const int g = lane >> 2, tg = lane & 3;
    const uint32_t zhb = smem_u32(zh), zlb = smem_u32(zl);

    float accG[2][8][4], accL[2][8][4];

    // --- weight copy macro: pre-converted [n][k] -> smem [n][136] ---
    #define COPY_W(slot) do {                                               \
        const __nv_bfloat16* _sH = g_wh + (slot)*16384;                     \
        const __nv_bfloat16* _sL = g_wl + (slot)*16384;                     \
        _Pragma("unroll")                                                   \
        for (int t = 0; t < 8; ++t) {                                       \
            const int idx = t*256 + tid;                                    \
            const int row = idx >> 4, seg = idx & 15;                       \
            cp16(whb + (uint32_t)(row*272 + seg*16), _sH + row*128 + seg*8);\
            cp16(wlb + (uint32_t)(row*272 + seg*16), _sL + row*128 + seg*8);\
        }                                                                   \
        CP_COMMIT(); CP_WAIT0();                                            \
    } while (0)

    // passes A and B: out = sigmoid(z@Wg) * (z@Wl) -> single fp16 plane
    for (int pass = 0; pass < 2; ++pass) {
        const int wg_slot = pass ? 2 : 0;   // wga / wgb
        const int wl_slot = pass ? 3 : 1;   // wa  / wb
        __half* outp = pass ? g_bf : g_af;

        __syncthreads();
        COPY_W(wg_slot);
        __syncthreads();
        mma_tile_k128(accG, zhb, zlb, whb, wlb, ib, jb, lane);
        __syncthreads();
        COPY_W(wl_slot);
        __syncthreads();
        mma_tile_k128(accL, zhb, zlb, whb, wlb, ib, jb, lane);
        __syncthreads();

        // combine + stage transposed [c][i] into w region (fp16 single)
        #pragma unroll
        for (int m = 0; m < 2; ++m)
            #pragma unroll
            for (int q = 0; q < 8; ++q) {
                const int cbase = jb + q*8 + tg*2;
                const int ibase = ib + m*16 + g;
                #pragma unroll
                for (int e = 0; e < 4; ++e) {
                    const int c  = cbase + (e & 1);
                    const int ii = ibase + 8 * (e >> 1);
                    const float v = sigmoidf(accG[m][q][e]) * accL[m][q][e];
                    stF[c*136 + ii] = __float2half_rn(v);
                }
            }
        __syncthreads();
        // coalesced plane stores (one fp16 plane)
        {
            const int c = tid >> 1, half = tid & 1;
            __half* dp = outp + (size_t)c * RTOT + r0 + half*64;
            #pragma unroll
            for (int bq = 0; bq < 8; ++bq)
                *(uint4*)(dp + bq*8) = *(const uint4*)&stF[c*136 + half*64 + bq*8];
        }
    }

    // gate pass: sigmoid(z @ w_gate) -> g_g row-major fp32
    __syncthreads();
    COPY_W(4);
    __syncthreads();
    mma_tile_k128(accG, zhb, zlb, whb, wlb, ib, jb, lane);

    #pragma unroll
    for (int m = 0; m < 2; ++m)
        #pragma unroll
        for (int q = 0; q < 8; ++q) {
            const int cc = jb + q*8 + tg*2;
            const size_t i1 = (size_t)(r0 + ib + m*16 + g);
            float2 v0, v1;
            v0.x = sigmoidf(accG[m][q][0]); v0.y = sigmoidf(accG[m][q][1]);
            v1.x = sigmoidf(accG[m][q][2]); v1.y = sigmoidf(accG[m][q][3]);
            *(float2*)(g_g + i1*CZc + cc)       = v0;
            *(float2*)(g_g + (i1 + 8)*CZc + cc) = v1;
        }
    #undef COPY_W
}

// ---------------------------------------------------------------------------
// Kernel 2: triangle einsum — SINGLE-product fp16 (3x fewer HMMA, half fill).
// K chunks of 64, smem [2][128][72] halves = 36864 B, 256 threads, occ 2.
// ---------------------------------------------------------------------------
__global__ __launch_bounds__(256, 2) void k_tri()
{
    extern __shared__ char sraw[];
    const uint32_t sb = smem_u32(sraw);

    const int tid  = threadIdx.x;
    const int lane = tid & 31, wid = tid >> 5;
    const int c  = blockIdx.z;
    const int i0 = blockIdx.y * 128;
    const int j0 = blockIdx.x * 128;
    const int wi = wid & 3, wj = wid >> 2;
    const int ib = wi * 32, jb = wj * 64;
    const int lrow = lane & 15;
    const uint32_t lcolb = (uint32_t)((lane >> 4) & 1) * 16u;

    const __half* bases[2] = {
        g_af + (size_t)c * RTOT + (size_t)i0 * NN,
        g_bf + (size_t)c * RTOT + (size_t)j0 * NN };

    float acc[2][8][4];
    #pragma unroll
    for (int m = 0; m < 2; ++m)
        #pragma unroll
        for (int q = 0; q < 8; ++q)
            #pragma unroll
            for (int e = 0; e < 4; ++e) acc[m][q][e] = 0.f;

    const int seg = tid & 7;
    for (int ch = 0; ch < 8; ++ch) {
        const int k0 = ch * 64;
        __syncthreads();
        #pragma unroll
        for (int e = 0; e < 8; ++e) {
            const int arr = e >> 2;
            const int row = ((e & 3) * 256 + tid) >> 3;
            cp16(sb + (uint32_t)(arr * 18432 + row * 144 + seg * 16),
                 bases[arr] + (size_t)row * NN + k0 + seg * 8);
        }
        CP_COMMIT();
        CP_WAIT0();
        __syncthreads();

        #pragma unroll
        for (int s = 0; s < 4; ++s) {
            const uint32_t colb = (uint32_t)s * 32u + lcolb;
            uint32_t Bf[4][4];
            #pragma unroll
            for (int p = 0; p < 4; ++p) {
                const uint32_t r = (uint32_t)(jb + p*16 + lrow);
                ldsm4(Bf[p], sb + 18432u + r*144u + colb);
            }
            #pragma unroll
            for (int m = 0; m < 2; ++m) {
                uint32_t Af[4];
                const uint32_t r = (uint32_t)(ib + m*16 + lrow);
                ldsm4(Af, sb + r*144u + colb);
                #pragma unroll
                for (int q = 0; q < 8; ++q) {
                    const int p = q >> 1, o = q & 1;
                    uint32_t v[2] = { Bf[p][o], Bf[p][o + 2] };
                    mma_f16(acc[m][q], Af, v);
                }
            }
        }
    }

    // epilogue -> g_upd fp32 plane
    {
        const int g = lane >> 2, tg = lane & 3;
        float* plane = g_upd + (size_t)c * RTOT;
        #pragma unroll
        for (int m = 0; m < 2; ++m) {
            const int irow = i0 + ib + m*16 + g;
            #pragma unroll
            for (int q = 0; q < 8; ++q) {
                const int jcol = j0 + jb + q*8 + tg*2;
                float2 v0; v0.x = acc[m][q][0]; v0.y = acc[m][q][1];
                float2 v1; v1.x = acc[m][q][2]; v1.y = acc[m][q][3];
                *(float2*)(plane + (size_t)irow       * NN + jcol) = v0;
                *(float2*)(plane + (size_t)(irow + 8) * NN + jcol) = v1;
            }
        }
    }
}

// ---------------------------------------------------------------------------
// Kernel 3 (R8/R12 verbatim): LN2(upd) @ w_out * gate -> out.
// 256 threads, 64-row tiles, occ 2.
// ---------------------------------------------------------------------------
__global__ __launch_bounds__(256, 2) void k_out(
    const float* __restrict__ gamma2,
    const float* __restrict__ beta2,
    float* __restrict__ out)
{
    extern __shared__ char sraw[];
    __nv_bfloat16* zh = (__nv_bfloat16*)sraw;
    __nv_bfloat16* zl = (__nv_bfloat16*)(sraw + 17408);
    float*         us = (float*)(sraw + 34816);
    const uint32_t sb  = smem_u32(sraw);
    const uint32_t zhb = sb, zlb = sb + 17408u;
    const uint32_t whb = sb + 69632u, wlb = sb + 88064u;

    const int tid  = threadIdx.x;
    const int lane = tid & 31, wid = tid >> 5;
    const int r0   = blockIdx.x * 64;
    const __nv_bfloat16* wsrcH = g_wh + 5*16384;
    const __nv_bfloat16* wsrcL = g_wl + 5*16384;

    // prefetch wout K-chunk 0
    #pragma unroll
    for (int t = 0; t < 4; ++t) {
        const int idx = t*256 + tid;
        const int row = idx >> 3, seg = idx & 7;
        cp16(whb + (uint32_t)(row*144 + seg*16), wsrcH + row*128 + seg*8);
        cp16(wlb + (uint32_t)(row*144 + seg*16), wsrcL + row*128 + seg*8);
    }
    CP_COMMIT();

    // load upd tile from planes: us[c][r], 64 rows
    #pragma unroll
    for (int e = 0; e < 8; ++e) {
        const int idx = e*256 + tid;
        const int cc = idx >> 4, r4 = (idx & 15) * 4;
        *(float4*)&us[cc*68 + r4] =
            *(const float4*)(g_upd + (size_t)cc * RTOT + r0 + r4);
    }
    __syncthreads();

    // LN over c, 4 threads per row (64 rows)
    {
        const int r = tid >> 2, q = tid & 3;
        float s = 0.f, s2 = 0.f;
        #pragma unroll 8
        for (int cc = 0; cc < 32; ++cc) {
            const float v = us[(q*32 + cc)*68 + r];
            s += v; s2 += v * v;
        }
        s  += __shfl_xor_sync(0xffffffffu, s,  1);
        s2 += __shfl_xor_sync(0xffffffffu, s2, 1);
        s  += __shfl_xor_sync(0xffffffffu, s,  2);
        s2 += __shfl_xor_sync(0xffffffffu, s2, 2);
        const float mu   = s * (1.0f / CZc);
        const float var  = s2 * (1.0f / CZc) - mu * mu;
        const float rstd = rsqrtf(var + 1e-5f);
        #pragma unroll 8
        for (int cc = 0; cc < 32; ++cc) {
            const int c = q*32 + cc;
            const float v = us[c*68 + r];
            const float z = (v - mu) * rstd * gamma2[c] + beta2[c];
            const __nv_bfloat16 hh = __float2bfloat16_rn(z);
            zh[r*136 + c] = hh;
            zl[r*136 + c] = __float2bfloat16_rn(z - __bfloat162float(hh));
        }
    }
    CP_WAIT0();
    __syncthreads();

    const int ib = (wid & 1) * 32, jb = (wid >> 1) * 32;
    float acc[2][4][4];
    #pragma unroll
    for (int m = 0; m < 2; ++m)
        #pragma unroll
        for (int q = 0; q < 4; ++q)
            #pragma unroll
            for (int e = 0; e < 4; ++e) acc[m][q][e] = 0.f;

    // chunk 0 (k 0..63)
    mma_k(acc, zhb, zlb, whb, wlb, 272u, 144u, 0u, 4, ib, jb, lane);
    __syncthreads();
    // load chunk 1, then accumulate
    #pragma unroll
    for (int t = 0; t < 4; ++t) {
        const int idx = t*256 + tid;
        const int row = idx >> 3, seg = idx & 7;
        cp16(whb + (uint32_t)(row*144 + seg*16), wsrcH + row*128 + 64 + seg*8);
        cp16(wlb + (uint32_t)(row*144 + seg*16), wsrcL + row*128 + 64 + seg*8);
    }
    CP_COMMIT();
    CP_WAIT0();
    __syncthreads();
    mma_k(acc, zhb, zlb, whb, wlb, 272u, 144u, 128u, 4, ib, jb, lane);

    // epilogue: gate multiply, fp32 row-major out
    {
        const int g = lane >> 2, tg = lane & 3;
        #pragma unroll
        for (int m = 0; m < 2; ++m)
            #pragma unroll
            for (int q = 0; q < 4; ++q) {
                const int cc = jb + q*8 + tg*2;
                const size_t i1 = (size_t)(r0 + ib + m*16 + g);
                const float2 gg0 = *(const float2*)(g_g + i1*CZc + cc);
                const float2 gg1 = *(const float2*)(g_g + (i1 + 8)*CZc + cc);
                float2 v0, v1;
                v0.x = gg0.x * acc[m][q][0]; v0.y = gg0.y * acc[m][q][1];
                v1.x = gg1.x * acc[m][q][2]; v1.y = gg1.y * acc[m][q][3];
                *(float2*)(out + i1*CZc + cc)       = v0;
                *(float2*)(out + (i1 + 8)*CZc + cc) = v1;
            }
    }
}

// ---------------------------------------------------------------------------
// Launch
// ---------------------------------------------------------------------------
extern "C" void kernel_launch(void* const* d_in, const int* in_sizes, int n_in,
                              void* d_out, int out_size)
{
    const float* x    = (const float*)d_in[0];
    const float* g1   = (const float*)d_in[1];
    const float* b1   = (const float*)d_in[2];
    const float* wga  = (const float*)d_in[3];
    const float* wgb  = (const float*)d_in[4];
    const float* wa   = (const float*)d_in[5];
    const float* wb   = (const float*)d_in[6];
    const float* g2   = (const float*)d_in[7];
    const float* b2   = (const float*)d_in[8];
    const float* wout = (const float*)d_in[9];
    const float* wg   = (const float*)d_in[10];

    cudaFuncSetAttribute(k_proj, cudaFuncAttributeMaxDynamicSharedMemorySize, 139264);
    cudaFuncSetAttribute(k_tri,  cudaFuncAttributeMaxDynamicSharedMemorySize, 36864);
    cudaFuncSetAttribute(k_out,  cudaFuncAttributeMaxDynamicSharedMemorySize, 106496);

    k_prep<<<6, 256>>>(wga, wa, wgb, wb, wg, wout);

    k_proj<<<RTOT / 128, 256, 139264>>>(x, g1, b1);

    dim3 grid(NN / 128, NN / 128, CZc);
    k_tri<<<grid, 256, 36864>>>();

    k_out<<<RTOT / 64, 256, 106496>>>(g2, b2, (float*)d_out);
}

// round 15
// speedup vs baseline: 1.5169x; 1.5169x over previous
#include <cuda_runtime.h>
#include <cuda_bf16.h>
#include <cuda_fp16.h>
#include <cstdint>

#define NN   512
#define CZc  128
#define RTOT (NN*NN)

// ---------------------------------------------------------------------------
// Scratch planes:
//   g_af/g_bf: fp16 single-precision channel planes [c][row];
//   per plane c: [i][k] (a), [j][k] (b).
//   g_upd fp32 planes [c][i][j]; g_g fp32 row-major [row][c].
//   g_wh/g_wl: pre-converted weights transposed [n][k] bf16 hi/lo.
//   Weight order: 0=wga 1=wa 2=wgb 3=wb 4=wg 5=wout.
// ---------------------------------------------------------------------------
__device__ __half g_af[(size_t)RTOT * CZc];
__device__ __half g_bf[(size_t)RTOT * CZc];
__device__ float g_g  [(size_t)RTOT * CZc];
__device__ float g_upd[(size_t)RTOT * CZc];
__device__ __nv_bfloat16 g_wh[6 * 128 * 128];
__device__ __nv_bfloat16 g_wl[6 * 128 * 128];

// ---------------------------------------------------------------------------
// Helpers (baseline ISA only)
// ---------------------------------------------------------------------------
__device__ __forceinline__ uint32_t smem_u32(const void* p) {
    uint32_t a;
    asm("{ .reg .u64 t; cvta.to.shared.u64 t, %1; cvt.u32.u64 %0, t; }"
        : "=r"(a) : "l"(p));
    return a;
}
__device__ __forceinline__ float sigmoidf(float x) { return 1.0f / (1.0f + __expf(-x)); }

__device__ __forceinline__ void ldsm4(uint32_t* r, uint32_t addr) {
    asm volatile("ldmatrix.sync.aligned.m8n8.x4.shared.b16 {%0,%1,%2,%3}, [%4];"
                 : "=r"(r[0]), "=r"(r[1]), "=r"(r[2]), "=r"(r[3]) : "r"(addr));
}
__device__ __forceinline__ void mma_bf16(float* c, const uint32_t* a, const uint32_t* b) {
    asm volatile(
        "mma.sync.aligned.m16n8k16.row.col.f32.bf16.bf16.f32 "
        "{%0,%1,%2,%3}, {%4,%5,%6,%7}, {%8,%9}, {%0,%1,%2,%3};"
        : "+f"(c[0]), "+f"(c[1]), "+f"(c[2]), "+f"(c[3])
        : "r"(a[0]), "r"(a[1]), "r"(a[2]), "r"(a[3]), "r"(b[0]), "r"(b[1]));
}
__device__ __forceinline__ void mma_f16(float* c, const uint32_t* a, const uint32_t* b) {
    asm volatile(
        "mma.sync.aligned.m16n8k16.row.col.f32.f16.f16.f32 "
        "{%0,%1,%2,%3}, {%4,%5,%6,%7}, {%8,%9}, {%0,%1,%2,%3};"
        : "+f"(c[0]), "+f"(c[1]), "+f"(c[2]), "+f"(c[3])
        : "r"(a[0]), "r"(a[1]), "r"(a[2]), "r"(a[3]), "r"(b[0]), "r"(b[1]));
}
__device__ __forceinline__ void cp16(uint32_t dst, const void* src) {
    asm volatile("cp.async.cg.shared.global [%0], [%1], 16;"
                 :: "r"(dst), "l"(src) : "memory");
}
#define CP_COMMIT() asm volatile("cp.async.commit_group;" ::: "memory")
#define CP_WAIT0()  asm volatile("cp.async.wait_group 0;"  ::: "memory")

// ---------------------------------------------------------------------------
// (R4) 128x128x128 bf16 hi/lo split mma: A [row][k], B [n][k], both 136-half
// rows (272B stride). 8 warps as 4(m) x 2(n): warp tile 32 x 64. Zeroes acc.
// ---------------------------------------------------------------------------
__device__ __forceinline__ void mma_tile_k128(
    float (*acc)[8][4],
    uint32_t a_h, uint32_t a_l, uint32_t b_h, uint32_t b_l,
    int ib, int jb, int lane)
{
    const int lrow = lane & 15;
    const uint32_t lcolb = (uint32_t)((lane >> 4) & 1) * 16u;

    #pragma unroll
    for (int m = 0; m < 2; ++m)
        #pragma unroll
        for (int q = 0; q < 8; ++q)
            #pragma unroll
            for (int e = 0; e < 4; ++e) acc[m][q][e] = 0.f;

    #pragma unroll
    for (int s = 0; s < 8; ++s) {
        const uint32_t colb = (uint32_t)s * 32u + lcolb;
        uint32_t Bh[4][4], Bl[4][4];
        #pragma unroll
        for (int p = 0; p < 4; ++p) {
            const uint32_t r = (uint32_t)(jb + p*16 + lrow);
            ldsm4(Bh[p], b_h + r*272u + colb);
            ldsm4(Bl[p], b_l + r*272u + colb);
        }
        #pragma unroll
        for (int m = 0; m < 2; ++m) {
            uint32_t Ah[4], Al[4];
            const uint32_t r = (uint32_t)(ib + m*16 + lrow);
            ldsm4(Ah, a_h + r*272u + colb);
            ldsm4(Al, a_l + r*272u + colb);
            #pragma unroll
            for (int q = 0; q < 8; ++q) {
                const int p = q >> 1, o = q & 1;
                uint32_t vh[2] = { Bh[p][o], Bh[p][o + 2] };
                uint32_t vl[2] = { Bl[p][o], Bl[p][o + 2] };
                mma_bf16(acc[m][q], Ah, vh);
                mma_bf16(acc[m][q], Ah, vl);
                mma_bf16(acc[m][q], Al, vh);
            }
        }
    }
}

// (R8) One K-span of 3-product hi/lo MMA for a 32x32 warp tile (k_out).
__device__ __forceinline__ void mma_k(
    float (*acc)[4][4],
    uint32_t aH, uint32_t aL, uint32_t bH, uint32_t bL,
    uint32_t astr, uint32_t bstr, uint32_t acol, int nsteps,
    int ib, int jb, int lane)
{
    const int lr = lane & 15;
    const uint32_t lc = (uint32_t)((lane >> 4) & 1) * 16u;
    for (int s = 0; s < nsteps; ++s) {
        const uint32_t colb = (uint32_t)s * 32u + lc;
        uint32_t Bh[2][4], Bl[2][4];
        #pragma unroll
        for (int p = 0; p < 2; ++p) {
            const uint32_t r = (uint32_t)(jb + p*16 + lr);
            ldsm4(Bh[p], bH + r*bstr + colb);
            ldsm4(Bl[p], bL + r*bstr + colb);
        }
        #pragma unroll
        for (int m = 0; m < 2; ++m) {
            uint32_t Ah[4], Al[4];
            const uint32_t r = (uint32_t)(ib + m*16 + lr);
            ldsm4(Ah, aH + r*astr + acol + colb);
            ldsm4(Al, aL + r*astr + acol + colb);
            #pragma unroll
            for (int q = 0; q < 4; ++q) {
                const int p = q >> 1, o = q & 1;
                uint32_t vh[2] = { Bh[p][o], Bh[p][o + 2] };
                uint32_t vl[2] = { Bl[p][o], Bl[p][o + 2] };
                mma_bf16(acc[m][q], Ah, vh);
                mma_bf16(acc[m][q], Ah, vl);
                mma_bf16(acc[m][q], Al, vh);
            }
        }
    }
}

// ---------------------------------------------------------------------------
// Kernel 0: pre-convert ALL 6 weights to transposed [n][k] bf16 hi/lo.
// ---------------------------------------------------------------------------
__global__ void k_prep(const float* __restrict__ w0, const float* __restrict__ w1,
                       const float* __restrict__ w2, const float* __restrict__ w3,
                       const float* __restrict__ w4, const float* __restrict__ w5)
{
    const float* tbl[6] = { w0, w1, w2, w3, w4, w5 };
    const float* W = tbl[blockIdx.x];
    __nv_bfloat16* oh = g_wh + blockIdx.x * 16384;
    __nv_bfloat16* ol = g_wl + blockIdx.x * 16384;
    for (int idx = threadIdx.x; idx < 16384; idx += 256) {
        const int n = idx >> 7, k = idx & 127;
        const float v = W[k * 128 + n];
        const __nv_bfloat16 h = __float2bfloat16_rn(v);
        oh[idx] = h;
        ol[idx] = __float2bfloat16_rn(v - __bfloat162float(h));
    }
}

// ---------------------------------------------------------------------------
// Kernel 1 (R14 verbatim): LN1 + 5 projections, cp.async weights,
// fp16 single-plane a/b epilogue.
// ---------------------------------------------------------------------------
__global__ __launch_bounds__(256, 1) void k_proj(
    const float* __restrict__ x,
    const float* __restrict__ gamma,
    const float* __restrict__ beta)
{
    extern __shared__ char sraw[];
    __nv_bfloat16* zh = (__nv_bfloat16*)sraw;            // [128][136]
    __nv_bfloat16* zl = zh + 128 * 136;
    float*         xs = (float*)(sraw + 69632);          // [128][136]
    __nv_bfloat16* wh = (__nv_bfloat16*)(sraw + 69632);  // [n][136]
    __nv_bfloat16* wl = wh + 128 * 136;
    __half*        stF = (__half*)(sraw + 69632);        // stage [c][136] fp16

    const int tid  = threadIdx.x;
    const int lane = tid & 31, wid = tid >> 5;
    const int r0   = blockIdx.x * 128;

    const uint32_t whb = smem_u32(wh), wlb = smem_u32(wl);

    // load x tile
    #pragma unroll
    for (int e = 0; e < 16; ++e) {
        const int idx = e * 256 + tid;
        const int r = idx >> 5, c4 = (idx & 31) * 4;
        *(float4*)&xs[r * 136 + c4] = *(const float4*)(x + (size_t)(r0 + r) * CZc + c4);
    }
    __syncthreads();

    // LN: warp handles 16 rows; write z as bf16 hi/lo
    {
        const float ga0 = gamma[lane],      ga1 = gamma[lane + 32];
        const float ga2 = gamma[lane + 64], ga3 = gamma[lane + 96];
        const float be0 = beta[lane],       be1 = beta[lane + 32];
        const float be2 = beta[lane + 64],  be3 = beta[lane + 96];
        for (int rr = 0; rr < 16; ++rr) {
            const int r = wid * 16 + rr;
            const float v0 = xs[r*136 + lane];
            const float v1 = xs[r*136 + lane + 32];
            const float v2 = xs[r*136 + lane + 64];
            const float v3 = xs[r*136 + lane + 96];
            float s  = v0 + v1 + v2 + v3;
            float s2 = v0*v0 + v1*v1 + v2*v2 + v3*v3;
            #pragma unroll
            for (int o = 16; o; o >>= 1) {
                s  += __shfl_xor_sync(0xffffffffu, s,  o);
                s2 += __shfl_xor_sync(0xffffffffu, s2, o);
            }
            const float mu   = s * (1.0f / CZc);
            const float var  = s2 * (1.0f / CZc) - mu * mu;
            const float rstd = rsqrtf(var + 1e-5f);
            const float z0 = (v0-mu)*rstd*ga0 + be0;
            const float z1 = (v1-mu)*rstd*ga1 + be1;
            const float z2 = (v2-mu)*rstd*ga2 + be2;
            const float z3 = (v3-mu)*rstd*ga3 + be3;
            #pragma unroll
            for (int j = 0; j < 4; ++j) {
                const float zv = j==0?z0:j==1?z1:j==2?z2:z3;
                const int c = lane + j*32;
                const __nv_bfloat16 h = __float2bfloat16_rn(zv);
                zh[r*136 + c] = h;
                zl[r*136 + c] = __float2bfloat16_rn(zv - __bfloat162float(h));
            }
        }
    }

    const int wi = wid & 3, wj = wid >> 2;
    const int ib = wi * 32, jb = wj * 64;
    const int g = lane >> 2, tg = lane & 3;
    const uint32_t zhb = smem_u32(zh), zlb = smem_u32(zl);

    float accG[2][8][4], accL[2][8][4];

    #define COPY_W(slot) do {                                               \
        const __nv_bfloat16* _sH = g_wh + (slot)*16384;                     \
        const __nv_bfloat16* _sL = g_wl + (slot)*16384;                     \
        _Pragma("unroll")                                                   \
        for (int t = 0; t < 8; ++t) {                                       \
            const int idx = t*256 + tid;                                    \
            const int row = idx >> 4, seg = idx & 15;                       \
            cp16(whb + (uint32_t)(row*272 + seg*16), _sH + row*128 + seg*8);\
            cp16(wlb + (uint32_t)(row*272 + seg*16), _sL + row*128 + seg*8);\
        }                                                                   \
        CP_COMMIT(); CP_WAIT0();                                            \
    } while (0)

    for (int pass = 0; pass < 2; ++pass) {
        const int wg_slot = pass ? 2 : 0;
        const int wl_slot = pass ? 3 : 1;
        __half* outp = pass ? g_bf : g_af;

        __syncthreads();
        COPY_W(wg_slot);
        __syncthreads();
        mma_tile_k128(accG, zhb, zlb, whb, wlb, ib, jb, lane);
        __syncthreads();
        COPY_W(wl_slot);
        __syncthreads();
        mma_tile_k128(accL, zhb, zlb, whb, wlb, ib, jb, lane);
        __syncthreads();

        #pragma unroll
        for (int m = 0; m < 2; ++m)
            #pragma unroll
            for (int q = 0; q < 8; ++q) {
                const int cbase = jb + q*8 + tg*2;
                const int ibase = ib + m*16 + g;
                #pragma unroll
                for (int e = 0; e < 4; ++e) {
                    const int c  = cbase + (e & 1);
                    const int ii = ibase + 8 * (e >> 1);
                    const float v = sigmoidf(accG[m][q][e]) * accL[m][q][e];
                    stF[c*136 + ii] = __float2half_rn(v);
                }
            }
        __syncthreads();
        {
            const int c = tid >> 1, half = tid & 1;
            __half* dp = outp + (size_t)c * RTOT + r0 + half*64;
            #pragma unroll
            for (int bq = 0; bq < 8; ++bq)
                *(uint4*)(dp + bq*8) = *(const uint4*)&stF[c*136 + half*64 + bq*8];
        }
    }

    __syncthreads();
    COPY_W(4);
    __syncthreads();
    mma_tile_k128(accG, zhb, zlb, whb, wlb, ib, jb, lane);

    #pragma unroll
    for (int m = 0; m < 2; ++m)
        #pragma unroll
        for (int q = 0; q < 8; ++q) {
            const int cc = jb + q*8 + tg*2;
            const size_t i1 = (size_t)(r0 + ib + m*16 + g);
            float2 v0, v1;
            v0.x = sigmoidf(accG[m][q][0]); v0.y = sigmoidf(accG[m][q][1]);
            v1.x = sigmoidf(accG[m][q][2]); v1.y = sigmoidf(accG[m][q][3]);
            *(float2*)(g_g + i1*CZc + cc)       = v0;
            *(float2*)(g_g + (i1 + 8)*CZc + cc) = v1;
        }
    #undef COPY_W
}

// ---------------------------------------------------------------------------
// Kernel 2: triangle einsum — single-product fp16, K chunks of 128.
// smem = A[128][136] + B[128][136] halves = 69632 B, 256 threads, occ 2.
// 4 chunks (vs 8): half the barriers / copy-wait exposures; 8 k16 steps
// of MMA per epoch.
// ---------------------------------------------------------------------------
__global__ __launch_bounds__(256, 2) void k_tri()
{
    extern __shared__ char sraw[];
    const uint32_t sb = smem_u32(sraw);

    const int tid  = threadIdx.x;
    const int lane = tid & 31, wid = tid >> 5;
    const int c  = blockIdx.z;
    const int i0 = blockIdx.y * 128;
    const int j0 = blockIdx.x * 128;
    const int wi = wid & 3, wj = wid >> 2;
    const int ib = wi * 32, jb = wj * 64;
    const int lrow = lane & 15;
    const uint32_t lcolb = (uint32_t)((lane >> 4) & 1) * 16u;

    const __half* Abase = g_af + (size_t)c * RTOT + (size_t)i0 * NN;
    const __half* Bbase = g_bf + (size_t)c * RTOT + (size_t)j0 * NN;

    float acc[2][8][4];
    #pragma unroll
    for (int m = 0; m < 2; ++m)
        #pragma unroll
        for (int q = 0; q < 8; ++q)
            #pragma unroll
            for (int e = 0; e < 4; ++e) acc[m][q][e] = 0.f;

    for (int ch = 0; ch < 4; ++ch) {
        const int k0 = ch * 128;
        __syncthreads();
        // fill: each array 128 rows x 256B (16 segs of 16B); 8 cp16/thread/array
        #pragma unroll
        for (int t = 0; t < 8; ++t) {
            const int idx = t*256 + tid;
            const int row = idx >> 4, seg = idx & 15;
            cp16(sb +          (uint32_t)(row*272 + seg*16),
                 Abase + (size_t)row * NN + k0 + seg*8);
            cp16(sb + 34816u + (uint32_t)(row*272 + seg*16),
                 Bbase + (size_t)row * NN + k0 + seg*8);
        }
        CP_COMMIT();
        CP_WAIT0();
        __syncthreads();

        #pragma unroll
        for (int s = 0; s < 8; ++s) {
            const uint32_t colb = (uint32_t)s * 32u + lcolb;
            uint32_t Bf[4][4];
            #pragma unroll
            for (int p = 0; p < 4; ++p) {
                const uint32_t r = (uint32_t)(jb + p*16 + lrow);
                ldsm4(Bf[p], sb + 34816u + r*272u + colb);
            }
            #pragma unroll
            for (int m = 0; m < 2; ++m) {
                uint32_t Af[4];
                const uint32_t r = (uint32_t)(ib + m*16 + lrow);
                ldsm4(Af, sb + r*272u + colb);
                #pragma unroll
                for (int q = 0; q < 8; ++q) {
                    const int p = q >> 1, o = q & 1;
                    uint32_t v[2] = { Bf[p][o], Bf[p][o + 2] };
                    mma_f16(acc[m][q], Af, v);
                }
            }
        }
    }

    // epilogue -> g_upd fp32 plane
    {
        const int g = lane >> 2, tg = lane & 3;
        float* plane = g_upd + (size_t)c * RTOT;
        #pragma unroll
        for (int m = 0; m < 2; ++m) {
            const int irow = i0 + ib + m*16 + g;
            #pragma unroll
            for (int q = 0; q < 8; ++q) {
                const int jcol = j0 + jb + q*8 + tg*2;
                float2 v0; v0.x = acc[m][q][0]; v0.y = acc[m][q][1];
                float2 v1; v1.x = acc[m][q][2]; v1.y = acc[m][q][3];
                *(float2*)(plane + (size_t)irow       * NN + jcol) = v0;
                *(float2*)(plane + (size_t)(irow + 8) * NN + jcol) = v1;
            }
        }
    }
}

// ---------------------------------------------------------------------------
// Kernel 3 (R8/R12 verbatim): LN2(upd) @ w_out * gate -> out.
// 256 threads, 64-row tiles, occ 2.
// ---------------------------------------------------------------------------
__global__ __launch_bounds__(256, 2) void k_out(
    const float* __restrict__ gamma2,
    const float* __restrict__ beta2,
    float* __restrict__ out)
{
    extern __shared__ char sraw[];
    __nv_bfloat16* zh = (__nv_bfloat16*)sraw;
    __nv_bfloat16* zl = (__nv_bfloat16*)(sraw + 17408);
    float*         us = (float*)(sraw + 34816);
    const uint32_t sb  = smem_u32(sraw);
    const uint32_t zhb = sb, zlb = sb + 17408u;
    const uint32_t whb = sb + 69632u, wlb = sb + 88064u;

    const int tid  = threadIdx.x;
    const int lane = tid & 31, wid = tid >> 5;
    const int r0   = blockIdx.x * 64;
    const __nv_bfloat16* wsrcH = g_wh + 5*16384;
    const __nv_bfloat16* wsrcL = g_wl + 5*16384;

    // prefetch wout K-chunk 0
    #pragma unroll
    for (int t = 0; t < 4; ++t) {
        const int idx = t*256 + tid;
        const int row = idx >> 3, seg = idx & 7;
        cp16(whb + (uint32_t)(row*144 + seg*16), wsrcH + row*128 + seg*8);
        cp16(wlb + (uint32_t)(row*144 + seg*16), wsrcL + row*128 + seg*8);
    }
    CP_COMMIT();

    // load upd tile from planes: us[c][r], 64 rows
    #pragma unroll
    for (int e = 0; e < 8; ++e) {
        const int idx = e*256 + tid;
        const int cc = idx >> 4, r4 = (idx & 15) * 4;
        *(float4*)&us[cc*68 + r4] =
            *(const float4*)(g_upd + (size_t)cc * RTOT + r0 + r4);
    }
    __syncthreads();

    // LN over c, 4 threads per row (64 rows)
    {
        const int r = tid >> 2, q = tid & 3;
        float s = 0.f, s2 = 0.f;
        #pragma unroll 8
        for (int cc = 0; cc < 32; ++cc) {
            const float v = us[(q*32 + cc)*68 + r];
            s += v; s2 += v * v;
        }
        s  += __shfl_xor_sync(0xffffffffu, s,  1);
        s2 += __shfl_xor_sync(0xffffffffu, s2, 1);
        s  += __shfl_xor_sync(0xffffffffu, s,  2);
        s2 += __shfl_xor_sync(0xffffffffu, s2, 2);
        const float mu   = s * (1.0f / CZc);
        const float var  = s2 * (1.0f / CZc) - mu * mu;
        const float rstd = rsqrtf(var + 1e-5f);
        #pragma unroll 8
        for (int cc = 0; cc < 32; ++cc) {
            const int c = q*32 + cc;
            const float v = us[c*68 + r];
            const float z = (v - mu) * rstd * gamma2[c] + beta2[c];
            const __nv_bfloat16 hh = __float2bfloat16_rn(z);
            zh[r*136 + c] = hh;
            zl[r*136 + c] = __float2bfloat16_rn(z - __bfloat162float(hh));
        }
    }
    CP_WAIT0();
    __syncthreads();

    const int ib = (wid & 1) * 32, jb = (wid >> 1) * 32;
    float acc[2][4][4];
    #pragma unroll
    for (int m = 0; m < 2; ++m)
        #pragma unroll
        for (int q = 0; q < 4; ++q)
            #pragma unroll
            for (int e = 0; e < 4; ++e) acc[m][q][e] = 0.f;

    // chunk 0 (k 0..63)
    mma_k(acc, zhb, zlb, whb, wlb, 272u, 144u, 0u, 4, ib, jb, lane);
    __syncthreads();
    // load chunk 1, then accumulate
    #pragma unroll
    for (int t = 0; t < 4; ++t) {
        const int idx = t*256 + tid;
        const int row = idx >> 3, seg = idx & 7;
        cp16(whb + (uint32_t)(row*144 + seg*16), wsrcH + row*128 + 64 + seg*8);
        cp16(wlb + (uint32_t)(row*144 + seg*16), wsrcL + row*128 + 64 + seg*8);
    }
    CP_COMMIT();
    CP_WAIT0();
    __syncthreads();
    mma_k(acc, zhb, zlb, whb, wlb, 272u, 144u, 128u, 4, ib, jb, lane);

    // epilogue: gate multiply, fp32 row-major out
    {
        const int g = lane >> 2, tg = lane & 3;
        #pragma unroll
        for (int m = 0; m < 2; ++m)
            #pragma unroll
            for (int q = 0; q < 4; ++q) {
                const int cc = jb + q*8 + tg*2;
                const size_t i1 = (size_t)(r0 + ib + m*16 + g);
                const float2 gg0 = *(const float2*)(g_g + i1*CZc + cc);
                const float2 gg1 = *(const float2*)(g_g + (i1 + 8)*CZc + cc);
                float2 v0, v1;
                v0.x = gg0.x * acc[m][q][0]; v0.y = gg0.y * acc[m][q][1];
                v1.x = gg1.x * acc[m][q][2]; v1.y = gg1.y * acc[m][q][3];
                *(float2*)(out + i1*CZc + cc)       = v0;
                *(float2*)(out + (i1 + 8)*CZc + cc) = v1;
            }
    }
}

// ---------------------------------------------------------------------------
// Launch
// ---------------------------------------------------------------------------
extern "C" void kernel_launch(void* const* d_in, const int* in_sizes, int n_in,
                              void* d_out, int out_size)
{
    const float* x    = (const float*)d_in[0];
    const float* g1   = (const float*)d_in[1];
    const float* b1   = (const float*)d_in[2];
    const float* wga  = (const float*)d_in[3];
    const float* wgb  = (const float*)d_in[4];
    const float* wa   = (const float*)d_in[5];
    const float* wb   = (const float*)d_in[6];
    const float* g2   = (const float*)d_in[7];
    const float* b2   = (const float*)d_in[8];
    const float* wout = (const float*)d_in[9];
    const float* wg   = (const float*)d_in[10];

    cudaFuncSetAttribute(k_proj, cudaFuncAttributeMaxDynamicSharedMemorySize, 139264);
    cudaFuncSetAttribute(k_tri,  cudaFuncAttributeMaxDynamicSharedMemorySize, 69632);
    cudaFuncSetAttribute(k_out,  cudaFuncAttributeMaxDynamicSharedMemorySize, 106496);

    k_prep<<<6, 256>>>(wga, wa, wgb, wb, wg, wout);

    k_proj<<<RTOT / 128, 256, 139264>>>(x, g1, b1);

    dim3 grid(NN / 128, NN / 128, CZc);
    k_tri<<<grid, 256, 69632>>>();

    k_out<<<RTOT / 64, 256, 106496>>>(g2, b2, (float*)d_out);
}

// round 16
// speedup vs baseline: 1.9694x; 1.2983x over previous
#include <cuda_runtime.h>
#include <cuda_bf16.h>
#include <cuda_fp16.h>
#include <cstdint>

#define NN   512
#define CZc  128
#define RTOT (NN*NN)

// ---------------------------------------------------------------------------
// Scratch planes:
//   g_af/g_bf: fp16 channel planes [c][row]; per plane c: [i][k] (a), [j][k] (b).
//   g_upd fp32 planes [c][i][j]; g_g fp32 row-major [row][c].
//   g_wf: fp16 weights transposed [n][k] (k_proj).
//   g_wh/g_wl: bf16 hi/lo weights transposed [n][k] (k_out uses slot 5).
//   Weight order: 0=wga 1=wa 2=wgb 3=wb 4=wg 5=wout.
// ---------------------------------------------------------------------------
__device__ __half g_af[(size_t)RTOT * CZc];
__device__ __half g_bf[(size_t)RTOT * CZc];
__device__ float g_g  [(size_t)RTOT * CZc];
__device__ float g_upd[(size_t)RTOT * CZc];
__device__ __half        g_wf[6 * 128 * 128];
__device__ __nv_bfloat16 g_wh[6 * 128 * 128];
__device__ __nv_bfloat16 g_wl[6 * 128 * 128];

// ---------------------------------------------------------------------------
// Helpers (baseline ISA only)
// ---------------------------------------------------------------------------
__device__ __forceinline__ uint32_t smem_u32(const void* p) {
    uint32_t a;
    asm("{ .reg .u64 t; cvta.to.shared.u64 t, %1; cvt.u32.u64 %0, t; }"
        : "=r"(a) : "l"(p));
    return a;
}
__device__ __forceinline__ float sigmoidf(float x) { return 1.0f / (1.0f + __expf(-x)); }

__device__ __forceinline__ void ldsm4(uint32_t* r, uint32_t addr) {
    asm volatile("ldmatrix.sync.aligned.m8n8.x4.shared.b16 {%0,%1,%2,%3}, [%4];"
                 : "=r"(r[0]), "=r"(r[1]), "=r"(r[2]), "=r"(r[3]) : "r"(addr));
}
__device__ __forceinline__ void mma_bf16(float* c, const uint32_t* a, const uint32_t* b) {
    asm volatile(
        "mma.sync.aligned.m16n8k16.row.col.f32.bf16.bf16.f32 "
        "{%0,%1,%2,%3}, {%4,%5,%6,%7}, {%8,%9}, {%0,%1,%2,%3};"
        : "+f"(c[0]), "+f"(c[1]), "+f"(c[2]), "+f"(c[3])
        : "r"(a[0]), "r"(a[1]), "r"(a[2]), "r"(a[3]), "r"(b[0]), "r"(b[1]));
}
__device__ __forceinline__ void mma_f16(float* c, const uint32_t* a, const uint32_t* b) {
    asm volatile(
        "mma.sync.aligned.m16n8k16.row.col.f32.f16.f16.f32 "
        "{%0,%1,%2,%3}, {%4,%5,%6,%7}, {%8,%9}, {%0,%1,%2,%3};"
        : "+f"(c[0]), "+f"(c[1]), "+f"(c[2]), "+f"(c[3])
        : "r"(a[0]), "r"(a[1]), "r"(a[2]), "r"(a[3]), "r"(b[0]), "r"(b[1]));
}
__device__ __forceinline__ void cp16(uint32_t dst, const void* src) {
    asm volatile("cp.async.cg.shared.global [%0], [%1], 16;"
                 :: "r"(dst), "l"(src) : "memory");
}
#define CP_COMMIT() asm volatile("cp.async.commit_group;" ::: "memory")
#define CP_WAIT0()  asm volatile("cp.async.wait_group 0;"  ::: "memory")

// ---------------------------------------------------------------------------
// fp16 single-product 128x128x128 tile: A [row][k], B [n][k], 272B row stride.
// 8 warps as 4(m) x 2(n): warp tile 32 x 64. Zeroes acc.
// ---------------------------------------------------------------------------
__device__ __forceinline__ void mma_tile_f16(
    float (*acc)[8][4], uint32_t a_f, uint32_t b_f, int ib, int jb, int lane)
{
    const int lrow = lane & 15;
    const uint32_t lcolb = (uint32_t)((lane >> 4) & 1) * 16u;

    #pragma unroll
    for (int m = 0; m < 2; ++m)
        #pragma unroll
        for (int q = 0; q < 8; ++q)
            #pragma unroll
            for (int e = 0; e < 4; ++e) acc[m][q][e] = 0.f;

    #pragma unroll
    for (int s = 0; s < 8; ++s) {
        const uint32_t colb = (uint32_t)s * 32u + lcolb;
        uint32_t Bf[4][4];
        #pragma unroll
        for (int p = 0; p < 4; ++p) {
            const uint32_t r = (uint32_t)(jb + p*16 + lrow);
            ldsm4(Bf[p], b_f + r*272u + colb);
        }
        #pragma unroll
        for (int m = 0; m < 2; ++m) {
            uint32_t Af[4];
            const uint32_t r = (uint32_t)(ib + m*16 + lrow);
            ldsm4(Af, a_f + r*272u + colb);
            #pragma unroll
            for (int q = 0; q < 8; ++q) {
                const int p = q >> 1, o = q & 1;
                uint32_t v[2] = { Bf[p][o], Bf[p][o + 2] };
                mma_f16(acc[m][q], Af, v);
            }
        }
    }
}

// (R8) One K-span of 3-product hi/lo MMA for a 32x32 warp tile (k_out).
__device__ __forceinline__ void mma_k(
    float (*acc)[4][4],
    uint32_t aH, uint32_t aL, uint32_t bH, uint32_t bL,
    uint32_t astr, uint32_t bstr, uint32_t acol, int nsteps,
    int ib, int jb, int lane)
{
    const int lr = lane & 15;
    const uint32_t lc = (uint32_t)((lane >> 4) & 1) * 16u;
    for (int s = 0; s < nsteps; ++s) {
        const uint32_t colb = (uint32_t)s * 32u + lc;
        uint32_t Bh[2][4], Bl[2][4];
        #pragma unroll
        for (int p = 0; p < 2; ++p) {
            const uint32_t r = (uint32_t)(jb + p*16 + lr);
            ldsm4(Bh[p], bH + r*bstr + colb);
            ldsm4(Bl[p], bL + r*bstr + colb);
        }
        #pragma unroll
        for (int m = 0; m < 2; ++m) {
            uint32_t Ah[4], Al[4];
            const uint32_t r = (uint32_t)(ib + m*16 + lr);
            ldsm4(Ah, aH + r*astr + acol + colb);
            ldsm4(Al, aL + r*astr + acol + colb);
            #pragma unroll
            for (int q = 0; q < 4; ++q) {
                const int p = q >> 1, o = q & 1;
                uint32_t vh[2] = { Bh[p][o], Bh[p][o + 2] };
                uint32_t vl[2] = { Bl[p][o], Bl[p][o + 2] };
                mma_bf16(acc[m][q], Ah, vh);
                mma_bf16(acc[m][q], Ah, vl);
                mma_bf16(acc[m][q], Al, vh);
            }
        }
    }
}

// ---------------------------------------------------------------------------
// Kernel 0: pre-convert weights: fp16 plane (k_proj) + bf16 hi/lo (k_out).
// All transposed [n][k].
// ---------------------------------------------------------------------------
__global__ void k_prep(const float* __restrict__ w0, const float* __restrict__ w1,
                       const float* __restrict__ w2, const float* __restrict__ w3,
                       const float* __restrict__ w4, const float* __restrict__ w5)
{
    const float* tbl[6] = { w0, w1, w2, w3, w4, w5 };
    const float* W = tbl[blockIdx.x];
    __half*        of = g_wf + blockIdx.x * 16384;
    __nv_bfloat16* oh = g_wh + blockIdx.x * 16384;
    __nv_bfloat16* ol = g_wl + blockIdx.x * 16384;
    for (int idx = threadIdx.x; idx < 16384; idx += 256) {
        const int n = idx >> 7, k = idx & 127;
        const float v = W[k * 128 + n];
        of[idx] = __float2half_rn(v);
        const __nv_bfloat16 h = __float2bfloat16_rn(v);
        oh[idx] = h;
        ol[idx] = __float2bfloat16_rn(v - __bfloat162float(h));
    }
}

// ---------------------------------------------------------------------------
// Kernel 1: LN1 + 5 projections — SINGLE-PRODUCT fp16 (3x fewer HMMA).
// smem (104448): zf@0 fp16 [128][136] (34816) |
//                region2@34816: xs fp32 [128][136] (69632);
//                  after LN: wf@34816 (34816), stage stF@69632 (34816).
// ---------------------------------------------------------------------------
__global__ __launch_bounds__(256, 1) void k_proj(
    const float* __restrict__ x,
    const float* __restrict__ gamma,
    const float* __restrict__ beta)
{
    extern __shared__ char sraw[];
    __half* zf  = (__half*)sraw;                 // [128][136] fp16
    float*  xs  = (float*)(sraw + 34816);        // [128][136] fp32
    __half* stF = (__half*)(sraw + 69632);       // stage [c][136] fp16

    const int tid  = threadIdx.x;
    const int lane = tid & 31, wid = tid >> 5;
    const int r0   = blockIdx.x * 128;

    const uint32_t sb  = smem_u32(sraw);
    const uint32_t zfb = sb;
    const uint32_t wfb = sb + 34816u;

    // load x tile
    #pragma unroll
    for (int e = 0; e < 16; ++e) {
        const int idx = e * 256 + tid;
        const int r = idx >> 5, c4 = (idx & 31) * 4;
        *(float4*)&xs[r * 136 + c4] = *(const float4*)(x + (size_t)(r0 + r) * CZc + c4);
    }
    __syncthreads();

    // LN: warp handles 16 rows; write z as fp16
    {
        const float ga0 = gamma[lane],      ga1 = gamma[lane + 32];
        const float ga2 = gamma[lane + 64], ga3 = gamma[lane + 96];
        const float be0 = beta[lane],       be1 = beta[lane + 32];
        const float be2 = beta[lane + 64],  be3 = beta[lane + 96];
        for (int rr = 0; rr < 16; ++rr) {
            const int r = wid * 16 + rr;
            const float v0 = xs[r*136 + lane];
            const float v1 = xs[r*136 + lane + 32];
            const float v2 = xs[r*136 + lane + 64];
            const float v3 = xs[r*136 + lane + 96];
            float s  = v0 + v1 + v2 + v3;
            float s2 = v0*v0 + v1*v1 + v2*v2 + v3*v3;
            #pragma unroll
            for (int o = 16; o; o >>= 1) {
                s  += __shfl_xor_sync(0xffffffffu, s,  o);
                s2 += __shfl_xor_sync(0xffffffffu, s2, o);
            }
            const float mu   = s * (1.0f / CZc);
            const float var  = s2 * (1.0f / CZc) - mu * mu;
            const float rstd = rsqrtf(var + 1e-5f);
            zf[r*136 + lane     ] = __float2half_rn((v0-mu)*rstd*ga0 + be0);
            zf[r*136 + lane + 32] = __float2half_rn((v1-mu)*rstd*ga1 + be1);
            zf[r*136 + lane + 64] = __float2half_rn((v2-mu)*rstd*ga2 + be2);
            zf[r*136 + lane + 96] = __float2half_rn((v3-mu)*rstd*ga3 + be3);
        }
    }
    __syncthreads();     // xs reads done; wf region free

    const int wi = wid & 3, wj = wid >> 2;
    const int ib = wi * 32, jb = wj * 64;
    const int g = lane >> 2, tg = lane & 3;

    float accG[2][8][4], accL[2][8][4];

    #define COPY_WF(slot) do {                                              \
        const __half* _sF = g_wf + (slot)*16384;                            \
        _Pragma("unroll")                                                   \
        for (int t = 0; t < 8; ++t) {                                       \
            const int idx = t*256 + tid;                                    \
            const int row = idx >> 4, seg = idx & 15;                       \
            cp16(wfb + (uint32_t)(row*272 + seg*16), _sF + row*128 + seg*8);\
        }                                                                   \
        CP_COMMIT(); CP_WAIT0();                                            \
    } while (0)

    for (int pass = 0; pass < 2; ++pass) {
        const int wg_slot = pass ? 2 : 0;
        const int wl_slot = pass ? 3 : 1;
        __half* outp = pass ? g_bf : g_af;

        COPY_WF(wg_slot);
        __syncthreads();
        mma_tile_f16(accG, zfb, wfb, ib, jb, lane);
        __syncthreads();
        COPY_WF(wl_slot);
        __syncthreads();
        mma_tile_f16(accL, zfb, wfb, ib, jb, lane);
        __syncthreads();

        // combine + stage transposed [c][i] (fp16)
        #pragma unroll
        for (int m = 0; m < 2; ++m)
            #pragma unroll
            for (int q = 0; q < 8; ++q) {
                const int cbase = jb + q*8 + tg*2;
                const int ibase = ib + m*16 + g;
                #pragma unroll
                for (int e = 0; e < 4; ++e) {
                    const int c  = cbase + (e & 1);
                    const int ii = ibase + 8 * (e >> 1);
                    const float v = sigmoidf(accG[m][q][e]) * accL[m][q][e];
                    stF[c*136 + ii] = __float2half_rn(v);
                }
            }
        __syncthreads();
        // coalesced plane stores
        {
            const int c = tid >> 1, half = tid & 1;
            __half* dp = outp + (size_t)c * RTOT + r0 + half*64;
            #pragma unroll
            for (int bq = 0; bq < 8; ++bq)
                *(uint4*)(dp + bq*8) = *(const uint4*)&stF[c*136 + half*64 + bq*8];
        }
        __syncthreads();   // stage reads done before next weight copy epoch
    }

    // gate pass: sigmoid(z @ w_gate) -> g_g row-major fp32
    COPY_WF(4);
    __syncthreads();
    mma_tile_f16(accG, zfb, wfb, ib, jb, lane);

    #pragma unroll
    for (int m = 0; m < 2; ++m)
        #pragma unroll
        for (int q = 0; q < 8; ++q) {
            const int cc = jb + q*8 + tg*2;
            const size_t i1 = (size_t)(r0 + ib + m*16 + g);
            float2 v0, v1;
            v0.x = sigmoidf(accG[m][q][0]); v0.y = sigmoidf(accG[m][q][1]);
            v1.x = sigmoidf(accG[m][q][2]); v1.y = sigmoidf(accG[m][q][3]);
            *(float2*)(g_g + i1*CZc + cc)       = v0;
            *(float2*)(g_g + (i1 + 8)*CZc + cc) = v1;
        }
    #undef COPY_WF
}

// ---------------------------------------------------------------------------
// Kernel 2 (R15 verbatim): triangle einsum — single-product fp16,
// K chunks of 128, smem 69632, 256 threads, occ 2.
// ---------------------------------------------------------------------------
__global__ __launch_bounds__(256, 2) void k_tri()
{
    extern __shared__ char sraw[];
    const uint32_t sb = smem_u32(sraw);

    const int tid  = threadIdx.x;
    const int lane = tid & 31, wid = tid >> 5;
    const int c  = blockIdx.z;
    const int i0 = blockIdx.y * 128;
    const int j0 = blockIdx.x * 128;
    const int wi = wid & 3, wj = wid >> 2;
    const int ib = wi * 32, jb = wj * 64;
    const int lrow = lane & 15;
    const uint32_t lcolb = (uint32_t)((lane >> 4) & 1) * 16u;

    const __half* Abase = g_af + (size_t)c * RTOT + (size_t)i0 * NN;
    const __half* Bbase = g_bf + (size_t)c * RTOT + (size_t)j0 * NN;

    float acc[2][8][4];
    #pragma unroll
    for (int m = 0; m < 2; ++m)
        #pragma unroll
        for (int q = 0; q < 8; ++q)
            #pragma unroll
            for (int e = 0; e < 4; ++e) acc[m][q][e] = 0.f;

    for (int ch = 0; ch < 4; ++ch) {
        const int k0 = ch * 128;
        __syncthreads();
        #pragma unroll
        for (int t = 0; t < 8; ++t) {
            const int idx = t*256 + tid;
            const int row = idx >> 4, seg = idx & 15;
            cp16(sb +          (uint32_t)(row*272 + seg*16),
                 Abase + (size_t)row * NN + k0 + seg*8);
            cp16(sb + 34816u + (uint32_t)(row*272 + seg*16),
                 Bbase + (size_t)row * NN + k0 + seg*8);
        }
        CP_COMMIT();
        CP_WAIT0();
        __syncthreads();

        #pragma unroll
        for (int s = 0; s < 8; ++s) {
            const uint32_t colb = (uint32_t)s * 32u + lcolb;
            uint32_t Bf[4][4];
            #pragma unroll
            for (int p = 0; p < 4; ++p) {
                const uint32_t r = (uint32_t)(jb + p*16 + lrow);
                ldsm4(Bf[p], sb + 34816u + r*272u + colb);
            }
            #pragma unroll
            for (int m = 0; m < 2; ++m) {
                uint32_t Af[4];
                const uint32_t r = (uint32_t)(ib + m*16 + lrow);
                ldsm4(Af, sb + r*272u + colb);
                #pragma unroll
                for (int q = 0; q < 8; ++q) {
                    const int p = q >> 1, o = q & 1;
                    uint32_t v[2] = { Bf[p][o], Bf[p][o + 2] };
                    mma_f16(acc[m][q], Af, v);
                }
            }
        }
    }

    // epilogue -> g_upd fp32 plane
    {
        const int g = lane >> 2, tg = lane & 3;
        float* plane = g_upd + (size_t)c * RTOT;
        #pragma unroll
        for (int m = 0; m < 2; ++m) {
            const int irow = i0 + ib + m*16 + g;
            #pragma unroll
            for (int q = 0; q < 8; ++q) {
                const int jcol = j0 + jb + q*8 + tg*2;
                float2 v0; v0.x = acc[m][q][0]; v0.y = acc[m][q][1];
                float2 v1; v1.x = acc[m][q][2]; v1.y = acc[m][q][3];
                *(float2*)(plane + (size_t)irow       * NN + jcol) = v0;
                *(float2*)(plane + (size_t)(irow + 8) * NN + jcol) = v1;
            }
        }
    }
}

// ---------------------------------------------------------------------------
// Kernel 3 (R8/R15 verbatim): LN2(upd) @ w_out * gate -> out.
// 256 threads, 64-row tiles, occ 2, bf16 hi/lo 3-product.
// ---------------------------------------------------------------------------
__global__ __launch_bounds__(256, 2) void k_out(
    const float* __restrict__ gamma2,
    const float* __restrict__ beta2,
    float* __restrict__ out)
{
    extern __shared__ char sraw[];
    __nv_bfloat16* zh = (__nv_bfloat16*)sraw;
    __nv_bfloat16* zl = (__nv_bfloat16*)(sraw + 17408);
    float*         us = (float*)(sraw + 34816);
    const uint32_t sb  = smem_u32(sraw);
    const uint32_t zhb = sb, zlb = sb + 17408u;
    const uint32_t whb = sb + 69632u, wlb = sb + 88064u;

    const int tid  = threadIdx.x;
    const int lane = tid & 31, wid = tid >> 5;
    const int r0   = blockIdx.x * 64;
    const __nv_bfloat16* wsrcH = g_wh + 5*16384;
    const __nv_bfloat16* wsrcL = g_wl + 5*16384;

    // prefetch wout K-chunk 0
    #pragma unroll
    for (int t = 0; t < 4; ++t) {
        const int idx = t*256 + tid;
        const int row = idx >> 3, seg = idx & 7;
        cp16(whb + (uint32_t)(row*144 + seg*16), wsrcH + row*128 + seg*8);
        cp16(wlb + (uint32_t)(row*144 + seg*16), wsrcL + row*128 + seg*8);
    }
    CP_COMMIT();

    // load upd tile from planes: us[c][r], 64 rows
    #pragma unroll
    for (int e = 0; e < 8; ++e) {
        const int idx = e*256 + tid;
        const int cc = idx >> 4, r4 = (idx & 15) * 4;
        *(float4*)&us[cc*68 + r4] =
            *(const float4*)(g_upd + (size_t)cc * RTOT + r0 + r4);
    }
    __syncthreads();

    // LN over c, 4 threads per row (64 rows)
    {
        const int r = tid >> 2, q = tid & 3;
        float s = 0.f, s2 = 0.f;
        #pragma unroll 8
        for (int cc = 0; cc < 32; ++cc) {
            const float v = us[(q*32 + cc)*68 + r];
            s += v; s2 += v * v;
        }
        s  += __shfl_xor_sync(0xffffffffu, s,  1);
        s2 += __shfl_xor_sync(0xffffffffu, s2, 1);
        s  += __shfl_xor_sync(0xffffffffu, s,  2);
        s2 += __shfl_xor_sync(0xffffffffu, s2, 2);
        const float mu   = s * (1.0f / CZc);
        const float var  = s2 * (1.0f / CZc) - mu * mu;
        const float rstd = rsqrtf(var + 1e-5f);
        #pragma unroll 8
        for (int cc = 0; cc < 32; ++cc) {
            const int c = q*32 + cc;
            const float v = us[c*68 + r];
            const float z = (v - mu) * rstd * gamma2[c] + beta2[c];
            const __nv_bfloat16 hh = __float2bfloat16_rn(z);
            zh[r*136 + c] = hh;
            zl[r*136 + c] = __float2bfloat16_rn(z - __bfloat162float(hh));
        }
    }
    CP_WAIT0();
    __syncthreads();

    const int ib = (wid & 1) * 32, jb = (wid >> 1) * 32;
    float acc[2][4][4];
    #pragma unroll
    for (int m = 0; m < 2; ++m)
        #pragma unroll
        for (int q = 0; q < 4; ++q)
            #pragma unroll
            for (int e = 0; e < 4; ++e) acc[m][q][e] = 0.f;

    // chunk 0 (k 0..63)
    mma_k(acc, zhb, zlb, whb, wlb, 272u, 144u, 0u, 4, ib, jb, lane);
    __syncthreads();
    // load chunk 1, then accumulate
    #pragma unroll
    for (int t = 0; t < 4; ++t) {
        const int idx = t*256 + tid;
        const int row = idx >> 3, seg = idx & 7;
        cp16(whb + (uint32_t)(row*144 + seg*16), wsrcH + row*128 + 64 + seg*8);
        cp16(wlb + (uint32_t)(row*144 + seg*16), wsrcL + row*128 + 64 + seg*8);
    }
    CP_COMMIT();
    CP_WAIT0();
    __syncthreads();
    mma_k(acc, zhb, zlb, whb, wlb, 272u, 144u, 128u, 4, ib, jb, lane);

    // epilogue: gate multiply, fp32 row-major out
    {
        const int g = lane >> 2, tg = lane & 3;
        #pragma unroll
        for (int m = 0; m < 2; ++m)
            #pragma unroll
            for (int q = 0; q < 4; ++q) {
                const int cc = jb + q*8 + tg*2;
                const size_t i1 = (size_t)(r0 + ib + m*16 + g);
                const float2 gg0 = *(const float2*)(g_g + i1*CZc + cc);
                const float2 gg1 = *(const float2*)(g_g + (i1 + 8)*CZc + cc);
                float2 v0, v1;
                v0.x = gg0.x * acc[m][q][0]; v0.y = gg0.y * acc[m][q][1];
                v1.x = gg1.x * acc[m][q][2]; v1.y = gg1.y * acc[m][q][3];
                *(float2*)(out + i1*CZc + cc)       = v0;
                *(float2*)(out + (i1 + 8)*CZc + cc) = v1;
            }
    }
}

// ---------------------------------------------------------------------------
// Launch
// ---------------------------------------------------------------------------
extern "C" void kernel_launch(void* const* d_in, const int* in_sizes, int n_in,
                              void* d_out, int out_size)
{
    const float* x    = (const float*)d_in[0];
    const float* g1   = (const float*)d_in[1];
    const float* b1   = (const float*)d_in[2];
    const float* wga  = (const float*)d_in[3];
    const float* wgb  = (const float*)d_in[4];
    const float* wa   = (const float*)d_in[5];
    const float* wb   = (const float*)d_in[6];
    const float* g2   = (const float*)d_in[7];
    const float* b2   = (const float*)d_in[8];
    const float* wout = (const float*)d_in[9];
    const float* wg   = (const float*)d_in[10];

    cudaFuncSetAttribute(k_proj, cudaFuncAttributeMaxDynamicSharedMemorySize, 104448);
    cudaFuncSetAttribute(k_tri,  cudaFuncAttributeMaxDynamicSharedMemorySize, 69632);
    cudaFuncSetAttribute(k_out,  cudaFuncAttributeMaxDynamicSharedMemorySize, 106496);

    k_prep<<<6, 256>>>(wga, wa, wgb, wb, wg, wout);

    k_proj<<<RTOT / 128, 256, 104448>>>(x, g1, b1);

    dim3 grid(NN / 128, NN / 128, CZc);
    k_tri<<<grid, 256, 69632>>>();

    k_out<<<RTOT / 64, 256, 106496>>>(g2, b2, (float*)d_out);
}

// round 17
// speedup vs baseline: 2.1264x; 1.0797x over previous
#include <cuda_runtime.h>
#include <cuda_bf16.h>
#include <cuda_fp16.h>
#include <cstdint>

#define NN   512
#define CZc  128
#define RTOT (NN*NN)

// ---------------------------------------------------------------------------
// Scratch planes:
//   g_af/g_bf: fp16 channel planes [c][row]; per plane c: [i][k] (a), [j][k] (b).
//   g_upd fp32 planes [c][i][j]; g_g fp32 row-major [row][c].
//   g_wf: fp16 weights transposed [n][k] (all kernels).
//   Weight order: 0=wga 1=wa 2=wgb 3=wb 4=wg 5=wout.
// ---------------------------------------------------------------------------
__device__ __half g_af[(size_t)RTOT * CZc];
__device__ __half g_bf[(size_t)RTOT * CZc];
__device__ float g_g  [(size_t)RTOT * CZc];
__device__ float g_upd[(size_t)RTOT * CZc];
__device__ __half g_wf[6 * 128 * 128];

// ---------------------------------------------------------------------------
// Helpers (baseline ISA only)
// ---------------------------------------------------------------------------
__device__ __forceinline__ uint32_t smem_u32(const void* p) {
    uint32_t a;
    asm("{ .reg .u64 t; cvta.to.shared.u64 t, %1; cvt.u32.u64 %0, t; }"
        : "=r"(a) : "l"(p));
    return a;
}
__device__ __forceinline__ float sigmoidf(float x) { return 1.0f / (1.0f + __expf(-x)); }

__device__ __forceinline__ void ldsm4(uint32_t* r, uint32_t addr) {
    asm volatile("ldmatrix.sync.aligned.m8n8.x4.shared.b16 {%0,%1,%2,%3}, [%4];"
                 : "=r"(r[0]), "=r"(r[1]), "=r"(r[2]), "=r"(r[3]) : "r"(addr));
}
__device__ __forceinline__ void mma_f16(float* c, const uint32_t* a, const uint32_t* b) {
    asm volatile(
        "mma.sync.aligned.m16n8k16.row.col.f32.f16.f16.f32 "
        "{%0,%1,%2,%3}, {%4,%5,%6,%7}, {%8,%9}, {%0,%1,%2,%3};"
        : "+f"(c[0]), "+f"(c[1]), "+f"(c[2]), "+f"(c[3])
        : "r"(a[0]), "r"(a[1]), "r"(a[2]), "r"(a[3]), "r"(b[0]), "r"(b[1]));
}
__device__ __forceinline__ void cp16(uint32_t dst, const void* src) {
    asm volatile("cp.async.cg.shared.global [%0], [%1], 16;"
                 :: "r"(dst), "l"(src) : "memory");
}
#define CP_COMMIT() asm volatile("cp.async.commit_group;" ::: "memory")
#define CP_WAIT0()  asm volatile("cp.async.wait_group 0;"  ::: "memory")

// ---------------------------------------------------------------------------
// fp16 single-product 128x128x128 tile: A [row][k], B [n][k], 272B row stride.
// 8 warps as 4(m) x 2(n): warp tile 32 x 64. Zeroes acc.
// ---------------------------------------------------------------------------
__device__ __forceinline__ void mma_tile_f16(
    float (*acc)[8][4], uint32_t a_f, uint32_t b_f, int ib, int jb, int lane)
{
    const int lrow = lane & 15;
    const uint32_t lcolb = (uint32_t)((lane >> 4) & 1) * 16u;

    #pragma unroll
    for (int m = 0; m < 2; ++m)
        #pragma unroll
        for (int q = 0; q < 8; ++q)
            #pragma unroll
            for (int e = 0; e < 4; ++e) acc[m][q][e] = 0.f;

    #pragma unroll
    for (int s = 0; s < 8; ++s) {
        const uint32_t colb = (uint32_t)s * 32u + lcolb;
        uint32_t Bf[4][4];
        #pragma unroll
        for (int p = 0; p < 4; ++p) {
            const uint32_t r = (uint32_t)(jb + p*16 + lrow);
            ldsm4(Bf[p], b_f + r*272u + colb);
        }
        #pragma unroll
        for (int m = 0; m < 2; ++m) {
            uint32_t Af[4];
            const uint32_t r = (uint32_t)(ib + m*16 + lrow);
            ldsm4(Af, a_f + r*272u + colb);
            #pragma unroll
            for (int q = 0; q < 8; ++q) {
                const int p = q >> 1, o = q & 1;
                uint32_t v[2] = { Bf[p][o], Bf[p][o + 2] };
                mma_f16(acc[m][q], Af, v);
            }
        }
    }
}

// fp16 single-product K=128 pass for a 32x32 warp tile (k_out).
// A rows [64][136] halves, B rows [128][136] halves, both 272B stride.
__device__ __forceinline__ void mma_k_f16(
    float (*acc)[4][4], uint32_t aF, uint32_t bF, int ib, int jb, int lane)
{
    const int lr = lane & 15;
    const uint32_t lc = (uint32_t)((lane >> 4) & 1) * 16u;
    #pragma unroll
    for (int m = 0; m < 2; ++m)
        #pragma unroll
        for (int q = 0; q < 4; ++q)
            #pragma unroll
            for (int e = 0; e < 4; ++e) acc[m][q][e] = 0.f;
    #pragma unroll
    for (int s = 0; s < 8; ++s) {
        const uint32_t colb = (uint32_t)s * 32u + lc;
        uint32_t Bf[2][4];
        #pragma unroll
        for (int p = 0; p < 2; ++p) {
            const uint32_t r = (uint32_t)(jb + p*16 + lr);
            ldsm4(Bf[p], bF + r*272u + colb);
        }
        #pragma unroll
        for (int m = 0; m < 2; ++m) {
            uint32_t Af[4];
            const uint32_t r = (uint32_t)(ib + m*16 + lr);
            ldsm4(Af, aF + r*272u + colb);
            #pragma unroll
            for (int q = 0; q < 4; ++q) {
                const int p = q >> 1, o = q & 1;
                uint32_t v[2] = { Bf[p][o], Bf[p][o + 2] };
                mma_f16(acc[m][q], Af, v);
            }
        }
    }
}

// ---------------------------------------------------------------------------
// Kernel 0: pre-convert weights to fp16 transposed [n][k].
// ---------------------------------------------------------------------------
__global__ void k_prep(const float* __restrict__ w0, const float* __restrict__ w1,
                       const float* __restrict__ w2, const float* __restrict__ w3,
                       const float* __restrict__ w4, const float* __restrict__ w5)
{
    const float* tbl[6] = { w0, w1, w2, w3, w4, w5 };
    const float* W = tbl[blockIdx.x];
    __half* of = g_wf + blockIdx.x * 16384;
    for (int idx = threadIdx.x; idx < 16384; idx += 256) {
        const int n = idx >> 7, k = idx & 127;
        of[idx] = __float2half_rn(W[k * 128 + n]);
    }
}

// ---------------------------------------------------------------------------
// Kernel 1 (R16 verbatim): LN1 + 5 projections — single-product fp16.
// smem (104448): zf@0 fp16 [128][136] | region2@34816: xs fp32 (69632);
//                after LN: wf@34816, stage stF@69632.
// ---------------------------------------------------------------------------
__global__ __launch_bounds__(256, 1) void k_proj(
    const float* __restrict__ x,
    const float* __restrict__ gamma,
    const float* __restrict__ beta)
{
    extern __shared__ char sraw[];
    __half* zf  = (__half*)sraw;                 // [128][136] fp16
    float*  xs  = (float*)(sraw + 34816);        // [128][136] fp32
    __half* stF = (__half*)(sraw + 69632);       // stage [c][136] fp16

    const int tid  = threadIdx.x;
    const int lane = tid & 31, wid = tid >> 5;
    const int r0   = blockIdx.x * 128;

    const uint32_t sb  = smem_u32(sraw);
    const uint32_t zfb = sb;
    const uint32_t wfb = sb + 34816u;

    // load x tile
    #pragma unroll
    for (int e = 0; e < 16; ++e) {
        const int idx = e * 256 + tid;
        const int r = idx >> 5, c4 = (idx & 31) * 4;
        *(float4*)&xs[r * 136 + c4] = *(const float4*)(x + (size_t)(r0 + r) * CZc + c4);
    }
    __syncthreads();

    // LN: warp handles 16 rows; write z as fp16
    {
        const float ga0 = gamma[lane],      ga1 = gamma[lane + 32];
        const float ga2 = gamma[lane + 64], ga3 = gamma[lane + 96];
        const float be0 = beta[lane],       be1 = beta[lane + 32];
        const float be2 = beta[lane + 64],  be3 = beta[lane + 96];
        for (int rr = 0; rr < 16; ++rr) {
            const int r = wid * 16 + rr;
            const float v0 = xs[r*136 + lane];
            const float v1 = xs[r*136 + lane + 32];
            const float v2 = xs[r*136 + lane + 64];
            const float v3 = xs[r*136 + lane + 96];
            float s  = v0 + v1 + v2 + v3;
            float s2 = v0*v0 + v1*v1 + v2*v2 + v3*v3;
            #pragma unroll
            for (int o = 16; o; o >>= 1) {
                s  += __shfl_xor_sync(0xffffffffu, s,  o);
                s2 += __shfl_xor_sync(0xffffffffu, s2, o);
            }
            const float mu   = s * (1.0f / CZc);
            const float var  = s2 * (1.0f / CZc) - mu * mu;
            const float rstd = rsqrtf(var + 1e-5f);
            zf[r*136 + lane     ] = __float2half_rn((v0-mu)*rstd*ga0 + be0);
            zf[r*136 + lane + 32] = __float2half_rn((v1-mu)*rstd*ga1 + be1);
            zf[r*136 + lane + 64] = __float2half_rn((v2-mu)*rstd*ga2 + be2);
            zf[r*136 + lane + 96] = __float2half_rn((v3-mu)*rstd*ga3 + be3);
        }
    }
    __syncthreads();     // xs reads done; wf region free

    const int wi = wid & 3, wj = wid >> 2;
    const int ib = wi * 32, jb = wj * 64;
    const int g = lane >> 2, tg = lane & 3;

    float accG[2][8][4], accL[2][8][4];

    #define COPY_WF(slot) do {                                              \
        const __half* _sF = g_wf + (slot)*16384;                            \
        _Pragma("unroll")                                                   \
        for (int t = 0; t < 8; ++t) {                                       \
            const int idx = t*256 + tid;                                    \
            const int row = idx >> 4, seg = idx & 15;                       \
            cp16(wfb + (uint32_t)(row*272 + seg*16), _sF + row*128 + seg*8);\
        }                                                                   \
        CP_COMMIT(); CP_WAIT0();                                            \
    } while (0)

    for (int pass = 0; pass < 2; ++pass) {
        const int wg_slot = pass ? 2 : 0;
        const int wl_slot = pass ? 3 : 1;
        __half* outp = pass ? g_bf : g_af;

        COPY_WF(wg_slot);
        __syncthreads();
        mma_tile_f16(accG, zfb, wfb, ib, jb, lane);
        __syncthreads();
        COPY_WF(wl_slot);
        __syncthreads();
        mma_tile_f16(accL, zfb, wfb, ib, jb, lane);
        __syncthreads();

        // combine + stage transposed [c][i] (fp16)
        #pragma unroll
        for (int m = 0; m < 2; ++m)
            #pragma unroll
            for (int q = 0; q < 8; ++q) {
                const int cbase = jb + q*8 + tg*2;
                const int ibase = ib + m*16 + g;
                #pragma unroll
                for (int e = 0; e < 4; ++e) {
                    const int c  = cbase + (e & 1);
                    const int ii = ibase + 8 * (e >> 1);
                    const float v = sigmoidf(accG[m][q][e]) * accL[m][q][e];
                    stF[c*136 + ii] = __float2half_rn(v);
                }
            }
        __syncthreads();
        // coalesced plane stores
        {
            const int c = tid >> 1, half = tid & 1;
            __half* dp = outp + (size_t)c * RTOT + r0 + half*64;
            #pragma unroll
            for (int bq = 0; bq < 8; ++bq)
                *(uint4*)(dp + bq*8) = *(const uint4*)&stF[c*136 + half*64 + bq*8];
        }
        __syncthreads();   // stage reads done before next weight copy epoch
    }

    // gate pass: sigmoid(z @ w_gate) -> g_g row-major fp32
    COPY_WF(4);
    __syncthreads();
    mma_tile_f16(accG, zfb, wfb, ib, jb, lane);

    #pragma unroll
    for (int m = 0; m < 2; ++m)
        #pragma unroll
        for (int q = 0; q < 8; ++q) {
            const int cc = jb + q*8 + tg*2;
            const size_t i1 = (size_t)(r0 + ib + m*16 + g);
            float2 v0, v1;
            v0.x = sigmoidf(accG[m][q][0]); v0.y = sigmoidf(accG[m][q][1]);
            v1.x = sigmoidf(accG[m][q][2]); v1.y = sigmoidf(accG[m][q][3]);
            *(float2*)(g_g + i1*CZc + cc)       = v0;
            *(float2*)(g_g + (i1 + 8)*CZc + cc) = v1;
        }
    #undef COPY_WF
}

// ---------------------------------------------------------------------------
// Kernel 2 (R15/R16 verbatim): triangle einsum — single-product fp16,
// K chunks of 128, smem 69632, 256 threads, occ 2.
// ---------------------------------------------------------------------------
__global__ __launch_bounds__(256, 2) void k_tri()
{
    extern __shared__ char sraw[];
    const uint32_t sb = smem_u32(sraw);

    const int tid  = threadIdx.x;
    const int lane = tid & 31, wid = tid >> 5;
    const int c  = blockIdx.z;
    const int i0 = blockIdx.y * 128;
    const int j0 = blockIdx.x * 128;
    const int wi = wid & 3, wj = wid >> 2;
    const int ib = wi * 32, jb = wj * 64;
    const int lrow = lane & 15;
    const uint32_t lcolb = (uint32_t)((lane >> 4) & 1) * 16u;

    const __half* Abase = g_af + (size_t)c * RTOT + (size_t)i0 * NN;
    const __half* Bbase = g_bf + (size_t)c * RTOT + (size_t)j0 * NN;

    float acc[2][8][4];
    #pragma unroll
    for (int m = 0; m < 2; ++m)
        #pragma unroll
        for (int q = 0; q < 8; ++q)
            #pragma unroll
            for (int e = 0; e < 4; ++e) acc[m][q][e] = 0.f;

    for (int ch = 0; ch < 4; ++ch) {
        const int k0 = ch * 128;
        __syncthreads();
        #pragma unroll
        for (int t = 0; t < 8; ++t) {
            const int idx = t*256 + tid;
            const int row = idx >> 4, seg = idx & 15;
            cp16(sb +          (uint32_t)(row*272 + seg*16),
                 Abase + (size_t)row * NN + k0 + seg*8);
            cp16(sb + 34816u + (uint32_t)(row*272 + seg*16),
                 Bbase + (size_t)row * NN + k0 + seg*8);
        }
        CP_COMMIT();
        CP_WAIT0();
        __syncthreads();

        #pragma unroll
        for (int s = 0; s < 8; ++s) {
            const uint32_t colb = (uint32_t)s * 32u + lcolb;
            uint32_t Bf[4][4];
            #pragma unroll
            for (int p = 0; p < 4; ++p) {
                const uint32_t r = (uint32_t)(jb + p*16 + lrow);
                ldsm4(Bf[p], sb + 34816u + r*272u + colb);
            }
            #pragma unroll
            for (int m = 0; m < 2; ++m) {
                uint32_t Af[4];
                const uint32_t r = (uint32_t)(ib + m*16 + lrow);
                ldsm4(Af, sb + r*272u + colb);
                #pragma unroll
                for (int q = 0; q < 8; ++q) {
                    const int p = q >> 1, o = q & 1;
                    uint32_t v[2] = { Bf[p][o], Bf[p][o + 2] };
                    mma_f16(acc[m][q], Af, v);
                }
            }
        }
    }

    // epilogue -> g_upd fp32 plane
    {
        const int g = lane >> 2, tg = lane & 3;
        float* plane = g_upd + (size_t)c * RTOT;
        #pragma unroll
        for (int m = 0; m < 2; ++m) {
            const int irow = i0 + ib + m*16 + g;
            #pragma unroll
            for (int q = 0; q < 8; ++q) {
                const int jcol = j0 + jb + q*8 + tg*2;
                float2 v0; v0.x = acc[m][q][0]; v0.y = acc[m][q][1];
                float2 v1; v1.x = acc[m][q][2]; v1.y = acc[m][q][3];
                *(float2*)(plane + (size_t)irow       * NN + jcol) = v0;
                *(float2*)(plane + (size_t)(irow + 8) * NN + jcol) = v1;
            }
        }
    }
}

// ---------------------------------------------------------------------------
// Kernel 3: LN2(upd) @ w_out * gate -> out — SINGLE-PRODUCT fp16.
// 256 threads, 64-row tiles, occ 2.
// smem (87040): zf@0 fp16 [64][136] (17408) | us@17408 fp32 [128][68] (34816)
//               | wf@52224 fp16 [128][136] (34816).
// wout prefetched whole at entry (overlaps upd load + LN).
// ---------------------------------------------------------------------------
__global__ __launch_bounds__(256, 2) void k_out(
    const float* __restrict__ gamma2,
    const float* __restrict__ beta2,
    float* __restrict__ out)
{
    extern __shared__ char sraw[];
    __half* zf = (__half*)sraw;                  // [64][136] fp16
    float*  us = (float*)(sraw + 17408);         // [128][68] fp32
    const uint32_t sb  = smem_u32(sraw);
    const uint32_t zfb = sb;
    const uint32_t wfb = sb + 52224u;

    const int tid  = threadIdx.x;
    const int lane = tid & 31, wid = tid >> 5;
    const int r0   = blockIdx.x * 64;
    const __half* wsrc = g_wf + 5*16384;

    // prefetch whole wout fp16 plane (overlaps upd load + LN)
    #pragma unroll
    for (int t = 0; t < 8; ++t) {
        const int idx = t*256 + tid;
        const int row = idx >> 4, seg = idx & 15;
        cp16(wfb + (uint32_t)(row*272 + seg*16), wsrc + row*128 + seg*8);
    }
    CP_COMMIT();

    // load upd tile from planes: us[c][r], 64 rows
    #pragma unroll
    for (int e = 0; e < 8; ++e) {
        const int idx = e*256 + tid;
        const int cc = idx >> 4, r4 = (idx & 15) * 4;
        *(float4*)&us[cc*68 + r4] =
            *(const float4*)(g_upd + (size_t)cc * RTOT + r0 + r4);
    }
    __syncthreads();

    // LN over c, 4 threads per row (64 rows); write z2 as fp16
    {
        const int r = tid >> 2, q = tid & 3;
        float s = 0.f, s2 = 0.f;
        #pragma unroll 8
        for (int cc = 0; cc < 32; ++cc) {
            const float v = us[(q*32 + cc)*68 + r];
            s += v; s2 += v * v;
        }
        s  += __shfl_xor_sync(0xffffffffu, s,  1);
        s2 += __shfl_xor_sync(0xffffffffu, s2, 1);
        s  += __shfl_xor_sync(0xffffffffu, s,  2);
        s2 += __shfl_xor_sync(0xffffffffu, s2, 2);
        const float mu   = s * (1.0f / CZc);
        const float var  = s2 * (1.0f / CZc) - mu * mu;
        const float rstd = rsqrtf(var + 1e-5f);
        #pragma unroll 8
        for (int cc = 0; cc < 32; ++cc) {
            const int c = q*32 + cc;
            const float v = us[c*68 + r];
            zf[r*136 + c] = __float2half_rn((v - mu) * rstd * gamma2[c] + beta2[c]);
        }
    }
    CP_WAIT0();
    __syncthreads();

    const int ib = (wid & 1) * 32, jb = (wid >> 1) * 32;
    float acc[2][4][4];
    mma_k_f16(acc, zfb, wfb, ib, jb, lane);

    // epilogue: gate multiply, fp32 row-major out
    {
        const int g = lane >> 2, tg = lane & 3;
        #pragma unroll
        for (int m = 0; m < 2; ++m)
            #pragma unroll
            for (int q = 0; q < 4; ++q) {
                const int cc = jb + q*8 + tg*2;
                const size_t i1 = (size_t)(r0 + ib + m*16 + g);
                const float2 gg0 = *(const float2*)(g_g + i1*CZc + cc);
                const float2 gg1 = *(const float2*)(g_g + (i1 + 8)*CZc + cc);
                float2 v0, v1;
                v0.x = gg0.x * acc[m][q][0]; v0.y = gg0.y * acc[m][q][1];
                v1.x = gg1.x * acc[m][q][2]; v1.y = gg1.y * acc[m][q][3];
                *(float2*)(out + i1*CZc + cc)       = v0;
                *(float2*)(out + (i1 + 8)*CZc + cc) = v1;
            }
    }
}

// ---------------------------------------------------------------------------
// Launch
// ---------------------------------------------------------------------------
extern "C" void kernel_launch(void* const* d_in, const int* in_sizes, int n_in,
                              void* d_out, int out_size)
{
    const float* x    = (const float*)d_in[0];
    const float* g1   = (const float*)d_in[1];
    const float* b1   = (const float*)d_in[2];
    const float* wga  = (const float*)d_in[3];
    const float* wgb  = (const float*)d_in[4];
    const float* wa   = (const float*)d_in[5];
    const float* wb   = (const float*)d_in[6];
    const float* g2   = (const float*)d_in[7];
    const float* b2   = (const float*)d_in[8];
    const float* wout = (const float*)d_in[9];
    const float* wg   = (const float*)d_in[10];

    cudaFuncSetAttribute(k_proj, cudaFuncAttributeMaxDynamicSharedMemorySize, 104448);
    cudaFuncSetAttribute(k_tri,  cudaFuncAttributeMaxDynamicSharedMemorySize, 69632);
    cudaFuncSetAttribute(k_out,  cudaFuncAttributeMaxDynamicSharedMemorySize, 87040);

    k_prep<<<6, 256>>>(wga, wa, wgb, wb, wg, wout);

    k_proj<<<RTOT / 128, 256, 104448>>>(x, g1, b1);

    dim3 grid(NN / 128, NN / 128, CZc);
    k_tri<<<grid, 256, 69632>>>();

    k_out<<<RTOT / 64, 256, 87040>>>(g2, b2, (float*)d_out);
}